// round 11
// baseline (speedup 1.0000x reference)
#include <cuda_runtime.h>
#include <cstdint>

// Energy-distance loss, tf32 mma.m16n8k8 with K-augmented norms:
//   A' = [-2a, na_hi, na_lo, 1, 1, pad0...]  (K = 72)
//   B' = [ b,   1,    1, nb_hi, nb_lo, pad0...]
//   acc = na + nb - 2 a.b  -> dist = sqrt.approx(acc)
// CTA 256 thr = A 128 x B 128; 8 warps 2(m) x 4(n), warp tile 64x32
// (mt=4, nt=4) for higher smem-fragment reuse. Warp-per-row prep.
// Global sums in double, one atomic per CTA.

#define NROWS 16384
#define MROWS 4096
#define DDIM  64
#define KDIM  72      // 64 data + 5 norm/one slots + 3 zero pad (9 k-steps)

__device__ double   g_acc[3];
__device__ uint32_t g_latA[NROWS * KDIM];   // A-role rows, k-interleaved
__device__ uint32_t g_latB[NROWS * KDIM];   // B-role rows
__device__ uint32_t g_zA[MROWS * KDIM];
__device__ uint32_t g_zB[MROWS * KDIM];

// smem words: A 128x72, B 128x72, red[8]
static constexpr int STRIDE  = KDIM;                 // 72 (==8 mod 32: conflict-free)
static constexpr int SM_B    = 128 * STRIDE;         // 9216
static constexpr int SM_RED  = SM_B + 128 * STRIDE;  // 18432
static constexpr int SM_WORDS = SM_RED + 8;
static constexpr int SM_BYTES = SM_WORDS * 4;        // 73760

// grid split (i-tiles 128 rows; j-tiles 128 rows)
static constexpr int G_CROSS = 128 * 32;             // 4096
static constexpr int G_LSELF = 8256;                 // sum_{bi<128}(128-bi)
static constexpr int G_ZSELF = 528;                  // sum_{bi<32}(32-bi)
static constexpr int G_ALL   = G_CROSS + G_LSELF + G_ZSELF;   // 12880

// ---------------------------------------------------------------------------
__device__ __forceinline__ uint32_t smem_u32(const void* p) {
    uint32_t a;
    asm("{ .reg .u64 t; cvta.to.shared.u64 t, %1; cvt.u32.u64 %0, t; }"
        : "=r"(a) : "l"(p));
    return a;
}
__device__ __forceinline__ void cp16(uint32_t saddr, const void* g) {
    asm volatile("cp.async.cg.shared.global [%0], [%1], 16;"
                 :: "r"(saddr), "l"(g));
}
__device__ __forceinline__ uint32_t to_tf32(float x) {
    uint32_t t;
    asm("cvt.rna.tf32.f32 %0, %1;" : "=r"(t) : "f"(x));
    return t;
}
__device__ __forceinline__ void mma_tf32(float* c, uint32_t a0, uint32_t a1,
                                         uint32_t a2, uint32_t a3,
                                         uint32_t b0, uint32_t b1) {
    asm volatile(
        "mma.sync.aligned.m16n8k8.row.col.f32.tf32.tf32.f32 "
        "{%0,%1,%2,%3}, {%4,%5,%6,%7}, {%8,%9}, {%0,%1,%2,%3};"
        : "+f"(c[0]), "+f"(c[1]), "+f"(c[2]), "+f"(c[3])
        : "r"(a0), "r"(a1), "r"(a2), "r"(a3), "r"(b0), "r"(b1));
}
__device__ __forceinline__ float sqrt_approx(float x) {
    float r;
    asm("sqrt.approx.f32 %0, %1;" : "=f"(r) : "f"(x));
    return r;
}

// k-interleave within each 8-col block: pairs (c, c+4) adjacent for LDS.64
__device__ __forceinline__ int ilv(int q) {
    return (q & ~7) + 2 * (q & 3) + ((q & 7) >> 2);
}

// ---------------------------------------------------------------------------
// prep: one WARP per row. Coalesced reads, shfl norm reduce, coalesced writes.
__global__ void prep_kernel(const float* __restrict__ lat,
                            const float* __restrict__ z) {
    const int gw = (blockIdx.x * blockDim.x + threadIdx.x) >> 5;
    const int lane = threadIdx.x & 31;
    if (gw == 0 && lane < 3) g_acc[lane] = 0.0;
    if (gw >= NROWS + MROWS) return;

    const float* src;
    uint32_t *dA, *dB;
    if (gw < NROWS) {
        src = lat + (size_t)gw * DDIM;
        dA = g_latA + (size_t)gw * KDIM;
        dB = g_latB + (size_t)gw * KDIM;
    } else {
        int rr = gw - NROWS;
        src = z + (size_t)rr * DDIM;
        dA = g_zA + (size_t)rr * KDIM;
        dB = g_zB + (size_t)rr * KDIM;
    }

    float x0 = src[lane];
    float x1 = src[lane + 32];
    float s = fmaf(x0, x0, x1 * x1);
#pragma unroll
    for (int off = 16; off; off >>= 1)
        s += __shfl_xor_sync(0xffffffffu, s, off);

    dA[ilv(lane)]      = to_tf32(-2.f * x0);
    dA[ilv(lane + 32)] = to_tf32(-2.f * x1);
    dB[ilv(lane)]      = to_tf32(x0);
    dB[ilv(lane + 32)] = to_tf32(x1);

    if (lane < 8) {
        uint32_t nh = to_tf32(s);
        uint32_t nl = to_tf32(s - __uint_as_float(nh));
        const uint32_t one = 0x3f800000u;
        uint32_t av = (lane == 0) ? nh : (lane == 1) ? nl : (lane < 4) ? one : 0u;
        uint32_t bv = (lane < 2) ? one : (lane == 2) ? nh : (lane == 3) ? nl : 0u;
        dA[ilv(64 + lane)] = av;
        dB[ilv(64 + lane)] = bv;
    }
}

// ---------------------------------------------------------------------------
// fused pair kernel. Segments (both tiles 128 rows):
//   [0, 4096)        cross:   128 i-tiles x 32 j-tiles
//   [4096, 12352)    latent self (triangular, p >= bi, TP=128)
//   [12352, 12880)   z self (triangular, TP=32)
// 256 threads, 8 warps 2(m) x 4(n); warp tile 64x32 (mt=4, nt=4).
__global__ __launch_bounds__(256, 2)
void pair_kernel() {
    extern __shared__ uint32_t smf[];
    uint32_t* sA = smf;
    uint32_t* sB = smf + SM_B;
    float* red = (float*)(smf + SM_RED);
    const uint32_t sbase = smem_u32(smf);

    const int tid = threadIdx.x, wid = tid >> 5, lane = tid & 31;
    const int wm = wid >> 2, wn = wid & 3;

    int bi, p, accIdx;
    bool self;
    const uint32_t *Abuf, *Bbuf;
    {
        int bid = blockIdx.x;
        if (bid < G_CROSS) {
            bi = bid >> 5; p = bid & 31;
            Abuf = g_latA; Bbuf = g_zB; accIdx = 0; self = false;
        } else if (bid < G_CROSS + G_LSELF) {
            int b = bid - G_CROSS;
            bi = 0;
            while (b >= 128 - bi) { b -= 128 - bi; bi++; }
            p = bi + b;
            Abuf = g_latA; Bbuf = g_latB; accIdx = 1; self = true;
        } else {
            int b = bid - (G_CROSS + G_LSELF);
            bi = 0;
            while (b >= 32 - bi) { b -= 32 - bi; bi++; }
            p = bi + b;
            Abuf = g_zA; Bbuf = g_zB; accIdx = 2; self = true;
        }
    }
    const int i0 = bi * 128;
    const int j0 = p * 128;
    const bool diag = self && (p == bi);

    // ---- async fill: A rows i0..+128, B rows j0..+128 (18 uint4/row) ----
    {
        const char* Ag = (const char*)(Abuf + (size_t)i0 * KDIM);
        const char* Bg = (const char*)(Bbuf + (size_t)j0 * KDIM);
#pragma unroll
        for (int it = 0; it < 9; it++) {
            int lin = tid + it * 256;            // 0..2303
            int row = lin / 18, c = lin % 18;
            uint32_t off = (uint32_t)(row * STRIDE + c * 4) * 4;
            cp16(sbase + off, Ag + (size_t)row * KDIM * 4 + c * 16);
            cp16(sbase + SM_B * 4 + off, Bg + (size_t)row * KDIM * 4 + c * 16);
        }
        asm volatile("cp.async.commit_group;");
        asm volatile("cp.async.wait_group 0;" ::: "memory");
    }
    __syncthreads();

    const int aBase = (wm * 64 + (lane >> 2)) * STRIDE + 2 * (lane & 3);
    const int bBase = (wn * 32 + (lane >> 2)) * STRIDE + 2 * (lane & 3);

    float acc[4][4][4];
#pragma unroll
    for (int mt = 0; mt < 4; mt++)
#pragma unroll
        for (int nt = 0; nt < 4; nt++)
#pragma unroll
            for (int e = 0; e < 4; e++) acc[mt][nt][e] = 0.f;

#pragma unroll
    for (int kb = 0; kb < 9; kb++) {
        const int ko = kb * 8;
        uint2 aLo[4], aHi[4];
#pragma unroll
        for (int mt = 0; mt < 4; mt++) {
            int o = aBase + mt * 16 * STRIDE + ko;
            aLo[mt] = *(const uint2*)(sA + o);
            aHi[mt] = *(const uint2*)(sA + o + 8 * STRIDE);
        }
        uint2 bv[4];
#pragma unroll
        for (int nt = 0; nt < 4; nt++)
            bv[nt] = *(const uint2*)(sB + bBase + nt * 8 * STRIDE + ko);
#pragma unroll
        for (int mt = 0; mt < 4; mt++)
#pragma unroll
            for (int nt = 0; nt < 4; nt++)
                mma_tf32(acc[mt][nt],
                         aLo[mt].x, aHi[mt].x, aLo[mt].y, aHi[mt].y,
                         bv[nt].x, bv[nt].y);
    }

    // ---- epilogue: acc IS sq; sqrt + accumulate (mask only on diag CTAs) ----
    float tot0 = 0.f, tot1 = 0.f;
    if (!diag) {
#pragma unroll
        for (int mt = 0; mt < 4; mt++)
#pragma unroll
            for (int nt = 0; nt < 4; nt++)
#pragma unroll
                for (int e = 0; e < 4; e += 2) {
                    tot0 += sqrt_approx(acc[mt][nt][e]);
                    tot1 += sqrt_approx(acc[mt][nt][e + 1]);
                }
    } else {
        const int ib = i0 + wm * 64 + (lane >> 2);
        const int jb = j0 + wn * 32 + (lane & 3) * 2;
#pragma unroll
        for (int mt = 0; mt < 4; mt++)
#pragma unroll
            for (int nt = 0; nt < 4; nt++)
#pragma unroll
                for (int e = 0; e < 4; e++) {
                    float dist = sqrt_approx(acc[mt][nt][e]);
                    int ii = ib + mt * 16 + (e >> 1) * 8;
                    int jj = jb + nt * 8 + (e & 1);
                    if (jj <= ii) dist = 0.f;   // strict upper; kills i==j NaN
                    if (e & 1) tot1 += dist; else tot0 += dist;
                }
    }

    // ---- block reduce, one double atomic per CTA ----
    float total = tot0 + tot1;
#pragma unroll
    for (int off = 16; off; off >>= 1)
        total += __shfl_xor_sync(0xffffffffu, total, off);
    if (lane == 0) red[wid] = total;
    __syncthreads();
    if (tid == 0) {
        double t = 0.0;
#pragma unroll
        for (int w = 0; w < 8; w++) t += (double)red[w];
        atomicAdd(&g_acc[accIdx], t);
    }
}

// ---------------------------------------------------------------------------
__global__ void finalize_kernel(float* out) {
    double a1 = g_acc[0] * (2.0 / ((double)NROWS * MROWS * DDIM));
    double b1 = g_acc[1] * (2.0 / ((double)NROWS * NROWS * DDIM));  // 2x: upper only
    double c1 = g_acc[2] * (2.0 / ((double)MROWS * MROWS * DDIM));
    out[0] = (float)(a1 - b1 - c1);
}

// ---------------------------------------------------------------------------
extern "C" void kernel_launch(void* const* d_in, const int* in_sizes, int n_in,
                              void* d_out, int out_size) {
    const float* lat = (const float*)d_in[0];
    const float* z   = (const float*)d_in[1];
    if (n_in >= 2 && in_sizes[0] == MROWS * DDIM && in_sizes[1] == NROWS * DDIM) {
        const float* t = lat; lat = z; z = t;
    }
    float* out = (float*)d_out;

    cudaFuncSetAttribute(pair_kernel,
                         cudaFuncAttributeMaxDynamicSharedMemorySize, SM_BYTES);

    prep_kernel<<<(32 * (NROWS + MROWS)) / 256, 256>>>(lat, z);
    pair_kernel<<<G_ALL, 256, SM_BYTES>>>();
    finalize_kernel<<<1, 1>>>(out);
}

// round 12
// speedup vs baseline: 1.5314x; 1.5314x over previous
#include <cuda_runtime.h>
#include <cuda_fp16.h>
#include <cstdint>

// Energy-distance loss, fp16 mma.m16n8k16 (fp32 accum) with K-augmented norms:
//   A' = [-2a (fp16), na_hi, na_lo, 1, 1, pad0...]   (K = 80, 5 k-steps)
//   B' = [  a (fp16),  1,    1,  nb_hi, nb_lo, pad0...]
//   acc = na + nb - 2 a.b  -> dist = sqrt.approx(acc)
// fp16 mantissa == tf32 mantissa (10 bits): same accuracy, half the MMAs/LDS.
// CTA 256 thr = A 128 x B 128 (two 64-row halves); 8 warps 4(m) x 2(n).
// Warp-per-row prep. Global sums in double, one atomic per CTA.

#define NROWS 16384
#define MROWS 4096
#define DDIM  64
#define KW    40      // words per row: 80 fp16 = 64 data + 4 aug + 12 pad

__device__ double   g_acc[3];
__device__ uint32_t g_latA[NROWS * KW];   // fp16x2 words, k-interleaved
__device__ uint32_t g_latB[NROWS * KW];
__device__ uint32_t g_zA[MROWS * KW];
__device__ uint32_t g_zB[MROWS * KW];

// smem words: A 128x40, B 128x40, red[8].  stride 40 == 8 mod 32: conflict-free
static constexpr int STRIDE  = KW;
static constexpr int SM_B    = 128 * STRIDE;         // 5120
static constexpr int SM_RED  = SM_B + 128 * STRIDE;  // 10240
static constexpr int SM_WORDS = SM_RED + 8;          // 10248
static constexpr int SM_BYTES = SM_WORDS * 4;        // 40992

// grid split (both tiles 128 rows)
static constexpr int G_CROSS = 128 * 32;             // 4096
static constexpr int G_LSELF = 8256;                 // sum_{bi<128}(128-bi)
static constexpr int G_ZSELF = 528;                  // sum_{bi<32}(32-bi)
static constexpr int G_ALL   = G_CROSS + G_LSELF + G_ZSELF;   // 12880

// ---------------------------------------------------------------------------
__device__ __forceinline__ uint32_t smem_u32(const void* p) {
    uint32_t a;
    asm("{ .reg .u64 t; cvta.to.shared.u64 t, %1; cvt.u32.u64 %0, t; }"
        : "=r"(a) : "l"(p));
    return a;
}
__device__ __forceinline__ void cp16(uint32_t saddr, const void* g) {
    asm volatile("cp.async.cg.shared.global [%0], [%1], 16;"
                 :: "r"(saddr), "l"(g));
}
__device__ __forceinline__ void mma_f16(float* c, uint32_t a0, uint32_t a1,
                                        uint32_t a2, uint32_t a3,
                                        uint32_t b0, uint32_t b1) {
    asm volatile(
        "mma.sync.aligned.m16n8k16.row.col.f32.f16.f16.f32 "
        "{%0,%1,%2,%3}, {%4,%5,%6,%7}, {%8,%9}, {%0,%1,%2,%3};"
        : "+f"(c[0]), "+f"(c[1]), "+f"(c[2]), "+f"(c[3])
        : "r"(a0), "r"(a1), "r"(a2), "r"(a3), "r"(b0), "r"(b1));
}
__device__ __forceinline__ float sqrt_approx(float x) {
    float r;
    asm("sqrt.approx.f32 %0, %1;" : "=f"(r) : "f"(x));
    return r;
}

// word interleave within each 8-word (16-k) block: logical word c ->
//   (c & ~7) + 2*(c&3) + ((c&7)>>2), so pairs (c, c+4) are adjacent -> LDS.64
__device__ __forceinline__ int ilvw(int c) {
    return (c & ~7) + 2 * (c & 3) + ((c & 7) >> 2);
}

// closed-form triangular decode: counts per bi are (C - bi);
// base(bi) = bi*C - bi*(bi-1)/2
__device__ __forceinline__ int tri_decode(int b, int C, int* rem) {
    float t = 2.f * C + 1.f;
    int bi = (int)((t - sqrtf(fmaxf(t * t - 8.f * (float)b, 0.f))) * 0.5f);
    if (bi < 0) bi = 0;
    if (bi > C - 1) bi = C - 1;
    while (bi > 0 && (bi * C - (bi * (bi - 1)) / 2) > b) --bi;
    while (((bi + 1) * C - ((bi + 1) * bi) / 2) <= b) ++bi;
    *rem = b - (bi * C - (bi * (bi - 1)) / 2);
    return bi;
}

// ---------------------------------------------------------------------------
// prep: one WARP per row. lane handles elements (2l, 2l+1) as one fp16x2 word.
__global__ void prep_kernel(const float* __restrict__ lat,
                            const float* __restrict__ z) {
    const int gw = (blockIdx.x * blockDim.x + threadIdx.x) >> 5;
    const int lane = threadIdx.x & 31;
    if (gw == 0 && lane < 3) g_acc[lane] = 0.0;
    if (gw >= NROWS + MROWS) return;

    const float* src;
    uint32_t *dA, *dB;
    if (gw < NROWS) {
        src = lat + (size_t)gw * DDIM;
        dA = g_latA + (size_t)gw * KW;
        dB = g_latB + (size_t)gw * KW;
    } else {
        int rr = gw - NROWS;
        src = z + (size_t)rr * DDIM;
        dA = g_zA + (size_t)rr * KW;
        dB = g_zB + (size_t)rr * KW;
    }

    float2 v = ((const float2*)src)[lane];
    float s = fmaf(v.x, v.x, v.y * v.y);
#pragma unroll
    for (int off = 16; off; off >>= 1)
        s += __shfl_xor_sync(0xffffffffu, s, off);

    __half2 hA = __floats2half2_rn(-2.f * v.x, -2.f * v.y);
    __half2 hB = __floats2half2_rn(v.x, v.y);
    int pos = ilvw(lane);
    dA[pos] = *(const uint32_t*)&hA;
    dB[pos] = *(const uint32_t*)&hB;

    if (lane < 8) {
        __half nh = __float2half_rn(s);
        __half nl = __float2half_rn(s - __half2float(nh));
        __half2 nrm = __halves2half2(nh, nl);
        const uint32_t ones = 0x3C003C00u;   // (1.0h, 1.0h)
        uint32_t nrm32 = *(const uint32_t*)&nrm;
        // word 32: A=(na_hi,na_lo) B=(1,1); word 33: A=(1,1) B=(nb_hi,nb_lo)
        uint32_t av = (lane == 0) ? nrm32 : (lane == 1) ? ones : 0u;
        uint32_t bv = (lane == 0) ? ones  : (lane == 1) ? nrm32 : 0u;
        int pa = 32 + 2 * (lane & 3) + (lane >> 2);
        dA[pa] = av;
        dB[pa] = bv;
    }
}

// ---------------------------------------------------------------------------
// fused pair kernel. Segments (both tiles 128 rows):
//   [0, 4096)        cross:   128 i-tiles x 32 j-tiles
//   [4096, 12352)    latent self (triangular, p >= bi, C=128)
//   [12352, 12880)   z self (triangular, C=32)
// 256 threads, 8 warps 4(m) x 2(n); per 64-row B half: warp 32x32 (mt2, nt4).
__global__ __launch_bounds__(256, 3)
void pair_kernel() {
    extern __shared__ uint32_t smf[];
    uint32_t* sA = smf;
    uint32_t* sB = smf + SM_B;
    float* red = (float*)(smf + SM_RED);
    const uint32_t sbase = smem_u32(smf);

    const int tid = threadIdx.x, wid = tid >> 5, lane = tid & 31;
    const int wm = wid >> 1, wn = wid & 1;

    int bi, p, accIdx;
    bool diag;
    const uint32_t *Abuf, *Bbuf;
    {
        int bid = blockIdx.x;
        if (bid < G_CROSS) {
            bi = bid >> 5; p = bid & 31;
            Abuf = g_latA; Bbuf = g_zB; accIdx = 0; diag = false;
        } else if (bid < G_CROSS + G_LSELF) {
            int rem;
            bi = tri_decode(bid - G_CROSS, 128, &rem);
            p = bi + rem;
            Abuf = g_latA; Bbuf = g_latB; accIdx = 1; diag = (rem == 0);
        } else {
            int rem;
            bi = tri_decode(bid - (G_CROSS + G_LSELF), 32, &rem);
            p = bi + rem;
            Abuf = g_zA; Bbuf = g_zB; accIdx = 2; diag = (rem == 0);
        }
    }
    const int i0 = bi * 128;
    const int j0 = p * 128;

    // ---- async fill: 128 rows x 10 uint4 each for A and B (5 iters) ----
    {
        const char* Ag = (const char*)(Abuf + (size_t)i0 * KW);
        const char* Bg = (const char*)(Bbuf + (size_t)j0 * KW);
#pragma unroll
        for (int it = 0; it < 5; it++) {
            int lin = tid + it * 256;            // 0..1279
            int row = lin / 10, c = lin % 10;
            uint32_t off = (uint32_t)(row * STRIDE + c * 4) * 4;
            cp16(sbase + off, Ag + (size_t)row * KW * 4 + c * 16);
            cp16(sbase + SM_B * 4 + off, Bg + (size_t)row * KW * 4 + c * 16);
        }
        asm volatile("cp.async.commit_group;");
        asm volatile("cp.async.wait_group 0;" ::: "memory");
    }
    __syncthreads();

    const int aBase = (wm * 32 + (lane >> 2)) * STRIDE + 2 * (lane & 3);
    const int bBase = (wn * 32 + (lane >> 2)) * STRIDE + 2 * (lane & 3);
    const int ib = i0 + wm * 32 + (lane >> 2);

    float tot0 = 0.f, tot1 = 0.f;

#pragma unroll
    for (int s = 0; s < 2; s++) {
        const uint32_t* sBt = sB + s * 64 * STRIDE;

        float acc[2][4][4];
#pragma unroll
        for (int mt = 0; mt < 2; mt++)
#pragma unroll
            for (int nt = 0; nt < 4; nt++)
#pragma unroll
                for (int e = 0; e < 4; e++) acc[mt][nt][e] = 0.f;

#pragma unroll
        for (int kb = 0; kb < 5; kb++) {
            const int ko = kb * 8;
            // LDS.64: .x = a0/a1 (k lo half), .y = a2/a3 (k hi half)
            uint2 aLo[2], aHi[2];
#pragma unroll
            for (int mt = 0; mt < 2; mt++) {
                int o = aBase + mt * 16 * STRIDE + ko;
                aLo[mt] = *(const uint2*)(sA + o);
                aHi[mt] = *(const uint2*)(sA + o + 8 * STRIDE);
            }
            uint2 bv[4];   // .x = b0, .y = b1
#pragma unroll
            for (int nt = 0; nt < 4; nt++)
                bv[nt] = *(const uint2*)(sBt + bBase + nt * 8 * STRIDE + ko);
#pragma unroll
            for (int mt = 0; mt < 2; mt++)
#pragma unroll
                for (int nt = 0; nt < 4; nt++)
                    mma_f16(acc[mt][nt],
                            aLo[mt].x, aHi[mt].x, aLo[mt].y, aHi[mt].y,
                            bv[nt].x, bv[nt].y);
        }

        // ---- epilogue: acc IS sq; sqrt + accumulate ----
        if (!diag) {
#pragma unroll
            for (int mt = 0; mt < 2; mt++)
#pragma unroll
                for (int nt = 0; nt < 4; nt++)
#pragma unroll
                    for (int e = 0; e < 4; e += 2) {
                        tot0 += sqrt_approx(acc[mt][nt][e]);
                        tot1 += sqrt_approx(acc[mt][nt][e + 1]);
                    }
        } else {
            const int jb = j0 + s * 64 + wn * 32 + (lane & 3) * 2;
#pragma unroll
            for (int mt = 0; mt < 2; mt++)
#pragma unroll
                for (int nt = 0; nt < 4; nt++)
#pragma unroll
                    for (int e = 0; e < 4; e++) {
                        float dist = sqrt_approx(acc[mt][nt][e]);
                        int ii = ib + mt * 16 + (e >> 1) * 8;
                        int jj = jb + nt * 8 + (e & 1);
                        if (jj <= ii) dist = 0.f;   // strict upper; kills i==j NaN
                        if (e & 1) tot1 += dist; else tot0 += dist;
                    }
        }
    }

    // ---- block reduce, one double atomic per CTA ----
    float total = tot0 + tot1;
#pragma unroll
    for (int off = 16; off; off >>= 1)
        total += __shfl_xor_sync(0xffffffffu, total, off);
    if (lane == 0) red[wid] = total;
    __syncthreads();
    if (tid == 0) {
        double t = 0.0;
#pragma unroll
        for (int w = 0; w < 8; w++) t += (double)red[w];
        atomicAdd(&g_acc[accIdx], t);
    }
}

// ---------------------------------------------------------------------------
__global__ void finalize_kernel(float* out) {
    double a1 = g_acc[0] * (2.0 / ((double)NROWS * MROWS * DDIM));
    double b1 = g_acc[1] * (2.0 / ((double)NROWS * NROWS * DDIM));  // 2x: upper only
    double c1 = g_acc[2] * (2.0 / ((double)MROWS * MROWS * DDIM));
    out[0] = (float)(a1 - b1 - c1);
}

// ---------------------------------------------------------------------------
extern "C" void kernel_launch(void* const* d_in, const int* in_sizes, int n_in,
                              void* d_out, int out_size) {
    const float* lat = (const float*)d_in[0];
    const float* z   = (const float*)d_in[1];
    if (n_in >= 2 && in_sizes[0] == MROWS * DDIM && in_sizes[1] == NROWS * DDIM) {
        const float* t = lat; lat = z; z = t;
    }
    float* out = (float*)d_out;

    cudaFuncSetAttribute(pair_kernel,
                         cudaFuncAttributeMaxDynamicSharedMemorySize, SM_BYTES);

    prep_kernel<<<(32 * (NROWS + MROWS)) / 256, 256>>>(lat, z);
    pair_kernel<<<G_ALL, 256, SM_BYTES>>>();
    finalize_kernel<<<1, 1>>>(out);
}

// round 13
// speedup vs baseline: 1.7501x; 1.1428x over previous
#include <cuda_runtime.h>
#include <cuda_fp16.h>
#include <cstdint>

// Energy-distance loss, fp16 mma.m16n8k16 (fp32 accum) with K-augmented norms:
//   A' = [-2a (fp16), na_hi, na_lo, 1, 1, pad0...]   (K = 80, 5 k-steps)
//   B' = [  a (fp16),  1,    1,  nb_hi, nb_lo, pad0...]
//   acc = na + nb - 2 a.b  -> dist = sqrt.approx(acc)
// CTA 256 thr = A 128 x B 256 (four 64-row halves); 8 warps 4(m) x 2(n).
// 3 CTAs/SM. Warp-per-row prep. Sums in double, one atomic per CTA.

#define NROWS 16384
#define MROWS 4096
#define DDIM  64
#define KW    40      // words per row: 80 fp16 = 64 data + 4 aug + 12 pad

__device__ double   g_acc[3];
__device__ uint32_t g_latA[NROWS * KW];   // fp16x2 words, k-interleaved
__device__ uint32_t g_latB[NROWS * KW];
__device__ uint32_t g_zA[MROWS * KW];
__device__ uint32_t g_zB[MROWS * KW];

// smem words: A 128x40, B 256x40, red[8].  stride 40 == 8 mod 32: conflict-free
static constexpr int STRIDE  = KW;
static constexpr int SM_B    = 128 * STRIDE;         // 5120
static constexpr int SM_RED  = SM_B + 256 * STRIDE;  // 15360
static constexpr int SM_WORDS = SM_RED + 8;          // 15368
static constexpr int SM_BYTES = SM_WORDS * 4;        // 61472

// grid split (i-tiles 128 rows; j-SUPER-tiles 256 rows)
static constexpr int G_CROSS = 128 * 16;             // 2048
static constexpr int G_LSELF = 4160;                 // sum_{bi<128}(64 - bi/2)
static constexpr int G_ZSELF = 272;                  // sum_{bi<32}(16 - bi/2)
static constexpr int G_ALL   = G_CROSS + G_LSELF + G_ZSELF;   // 6480

// ---------------------------------------------------------------------------
__device__ __forceinline__ uint32_t smem_u32(const void* p) {
    uint32_t a;
    asm("{ .reg .u64 t; cvta.to.shared.u64 t, %1; cvt.u32.u64 %0, t; }"
        : "=r"(a) : "l"(p));
    return a;
}
__device__ __forceinline__ void cp16(uint32_t saddr, const void* g) {
    asm volatile("cp.async.cg.shared.global [%0], [%1], 16;"
                 :: "r"(saddr), "l"(g));
}
__device__ __forceinline__ void mma_f16(float* c, uint32_t a0, uint32_t a1,
                                        uint32_t a2, uint32_t a3,
                                        uint32_t b0, uint32_t b1) {
    asm volatile(
        "mma.sync.aligned.m16n8k16.row.col.f32.f16.f16.f32 "
        "{%0,%1,%2,%3}, {%4,%5,%6,%7}, {%8,%9}, {%0,%1,%2,%3};"
        : "+f"(c[0]), "+f"(c[1]), "+f"(c[2]), "+f"(c[3])
        : "r"(a0), "r"(a1), "r"(a2), "r"(a3), "r"(b0), "r"(b1));
}
__device__ __forceinline__ float sqrt_approx(float x) {
    float r;
    asm("sqrt.approx.f32 %0, %1;" : "=f"(r) : "f"(x));
    return r;
}

// word interleave within each 8-word (16-k) block: pairs (c, c+4) adjacent
__device__ __forceinline__ int ilvw(int c) {
    return (c & ~7) + 2 * (c & 3) + ((c & 7) >> 2);
}

// decode for counts c(bi) = T - (bi>>1):
//   base(bi) = T*bi - s(bi), s(2m) = m(m-1), s(2m+1) = m*m
__device__ __forceinline__ int base_half(int bi, int T) {
    int m = bi >> 1;
    int s = (bi & 1) ? m * m : m * (m - 1);
    return T * bi - s;
}
__device__ __forceinline__ int tri2_decode(int b, int T, int* rem) {
    float Tf = (float)T;
    int bi = (int)(2.f * (Tf - sqrtf(fmaxf(Tf * Tf - (float)b, 0.f))));
    if (bi < 0) bi = 0;
    if (bi > 2 * T - 1) bi = 2 * T - 1;
    while (bi > 0 && base_half(bi, T) > b) --bi;
    while (base_half(bi + 1, T) <= b) ++bi;
    *rem = b - base_half(bi, T);
    return bi;
}

// ---------------------------------------------------------------------------
// prep: one WARP per row. lane handles elements (2l, 2l+1) as one fp16x2 word.
__global__ void prep_kernel(const float* __restrict__ lat,
                            const float* __restrict__ z) {
    const int gw = (blockIdx.x * blockDim.x + threadIdx.x) >> 5;
    const int lane = threadIdx.x & 31;
    if (gw == 0 && lane < 3) g_acc[lane] = 0.0;
    if (gw >= NROWS + MROWS) return;

    const float* src;
    uint32_t *dA, *dB;
    if (gw < NROWS) {
        src = lat + (size_t)gw * DDIM;
        dA = g_latA + (size_t)gw * KW;
        dB = g_latB + (size_t)gw * KW;
    } else {
        int rr = gw - NROWS;
        src = z + (size_t)rr * DDIM;
        dA = g_zA + (size_t)rr * KW;
        dB = g_zB + (size_t)rr * KW;
    }

    float2 v = ((const float2*)src)[lane];
    float s = fmaf(v.x, v.x, v.y * v.y);
#pragma unroll
    for (int off = 16; off; off >>= 1)
        s += __shfl_xor_sync(0xffffffffu, s, off);

    __half2 hA = __floats2half2_rn(-2.f * v.x, -2.f * v.y);
    __half2 hB = __floats2half2_rn(v.x, v.y);
    int pos = ilvw(lane);
    dA[pos] = *(const uint32_t*)&hA;
    dB[pos] = *(const uint32_t*)&hB;

    if (lane < 8) {
        __half nh = __float2half_rn(s);
        __half nl = __float2half_rn(s - __half2float(nh));
        __half2 nrm = __halves2half2(nh, nl);
        const uint32_t ones = 0x3C003C00u;   // (1.0h, 1.0h)
        uint32_t nrm32 = *(const uint32_t*)&nrm;
        // word 32: A=(na_hi,na_lo) B=(1,1); word 33: A=(1,1) B=(nb_hi,nb_lo)
        uint32_t av = (lane == 0) ? nrm32 : (lane == 1) ? ones : 0u;
        uint32_t bv = (lane == 0) ? ones  : (lane == 1) ? nrm32 : 0u;
        int pa = 32 + 2 * (lane & 3) + (lane >> 2);
        dA[pa] = av;
        dB[pa] = bv;
    }
}

// ---------------------------------------------------------------------------
// fused pair kernel. Segments (i-tiles 128 rows, j-super-tiles 256 rows):
//   [0, 2048)       cross:   128 i-tiles x 16 super-tiles
//   [2048, 6208)    latent self (p >= bi/2, per-128-subtile skip/diag, T=64)
//   [6208, 6480)    z self (T=16)
// 256 threads, 8 warps 4(m) x 2(n); per 64-row half: warp 32x32 (mt2, nt4).
__global__ __launch_bounds__(256, 3)
void pair_kernel() {
    extern __shared__ uint32_t smf[];
    uint32_t* sA = smf;
    uint32_t* sB = smf + SM_B;
    float* red = (float*)(smf + SM_RED);
    const uint32_t sbase = smem_u32(smf);

    const int tid = threadIdx.x, wid = tid >> 5, lane = tid & 31;
    const int wm = wid >> 1, wn = wid & 1;

    int bi, p, accIdx;
    bool self;
    const uint32_t *Abuf, *Bbuf;
    {
        int bid = blockIdx.x;
        if (bid < G_CROSS) {
            bi = bid >> 4; p = bid & 15;
            Abuf = g_latA; Bbuf = g_zB; accIdx = 0; self = false;
        } else if (bid < G_CROSS + G_LSELF) {
            int rem;
            bi = tri2_decode(bid - G_CROSS, 64, &rem);
            p = (bi >> 1) + rem;
            Abuf = g_latA; Bbuf = g_latB; accIdx = 1; self = true;
        } else {
            int rem;
            bi = tri2_decode(bid - (G_CROSS + G_LSELF), 16, &rem);
            p = (bi >> 1) + rem;
            Abuf = g_zA; Bbuf = g_zB; accIdx = 2; self = true;
        }
    }
    const int i0 = bi * 128;
    const int j0 = p * 256;

    // ---- async fill: A 128 rows (1280 chunks), B 256 rows (2560 chunks) ----
    {
        const char* Ag = (const char*)(Abuf + (size_t)i0 * KW);
        const char* Bg = (const char*)(Bbuf + (size_t)j0 * KW);
#pragma unroll
        for (int it = 0; it < 5; it++) {
            int lin = tid + it * 256;            // 0..1279
            int row = lin / 10, c = lin % 10;
            cp16(sbase + (uint32_t)(row * STRIDE + c * 4) * 4,
                 Ag + (size_t)row * KW * 4 + c * 16);
        }
#pragma unroll
        for (int it = 0; it < 10; it++) {
            int lin = tid + it * 256;            // 0..2559
            int row = lin / 10, c = lin % 10;
            cp16(sbase + (uint32_t)(SM_B + row * STRIDE + c * 4) * 4,
                 Bg + (size_t)row * KW * 4 + c * 16);
        }
        asm volatile("cp.async.commit_group;");
        asm volatile("cp.async.wait_group 0;" ::: "memory");
    }
    __syncthreads();

    const int aBase = (wm * 32 + (lane >> 2)) * STRIDE + 2 * (lane & 3);
    const int bBase = (wn * 32 + (lane >> 2)) * STRIDE + 2 * (lane & 3);
    const int ib = i0 + wm * 32 + (lane >> 2);

    float tot0 = 0.f, tot1 = 0.f;

#pragma unroll
    for (int s = 0; s < 4; s++) {
        const int j128 = 2 * p + (s >> 1);       // 128-row j-subtile index
        if (self && j128 < bi) continue;          // below diagonal: skip whole half
        const bool diag = self && (j128 == bi);
        const uint32_t* sBt = sB + s * 64 * STRIDE;

        float acc[2][4][4];
#pragma unroll
        for (int mt = 0; mt < 2; mt++)
#pragma unroll
            for (int nt = 0; nt < 4; nt++)
#pragma unroll
                for (int e = 0; e < 4; e++) acc[mt][nt][e] = 0.f;

#pragma unroll
        for (int kb = 0; kb < 5; kb++) {
            const int ko = kb * 8;
            uint2 aLo[2], aHi[2];
#pragma unroll
            for (int mt = 0; mt < 2; mt++) {
                int o = aBase + mt * 16 * STRIDE + ko;
                aLo[mt] = *(const uint2*)(sA + o);
                aHi[mt] = *(const uint2*)(sA + o + 8 * STRIDE);
            }
            uint2 bv[4];
#pragma unroll
            for (int nt = 0; nt < 4; nt++)
                bv[nt] = *(const uint2*)(sBt + bBase + nt * 8 * STRIDE + ko);
#pragma unroll
            for (int mt = 0; mt < 2; mt++)
#pragma unroll
                for (int nt = 0; nt < 4; nt++)
                    mma_f16(acc[mt][nt],
                            aLo[mt].x, aHi[mt].x, aLo[mt].y, aHi[mt].y,
                            bv[nt].x, bv[nt].y);
        }

        // ---- epilogue: acc IS sq; sqrt + accumulate ----
        if (!diag) {
#pragma unroll
            for (int mt = 0; mt < 2; mt++)
#pragma unroll
                for (int nt = 0; nt < 4; nt++)
#pragma unroll
                    for (int e = 0; e < 4; e += 2) {
                        tot0 += sqrt_approx(acc[mt][nt][e]);
                        tot1 += sqrt_approx(acc[mt][nt][e + 1]);
                    }
        } else {
            const int jb = j0 + s * 64 + wn * 32 + (lane & 3) * 2;
#pragma unroll
            for (int mt = 0; mt < 2; mt++)
#pragma unroll
                for (int nt = 0; nt < 4; nt++)
#pragma unroll
                    for (int e = 0; e < 4; e++) {
                        float dist = sqrt_approx(acc[mt][nt][e]);
                        int ii = ib + mt * 16 + (e >> 1) * 8;
                        int jj = jb + nt * 8 + (e & 1);
                        if (jj <= ii) dist = 0.f;   // strict upper; kills i==j NaN
                        if (e & 1) tot1 += dist; else tot0 += dist;
                    }
        }
    }

    // ---- block reduce, one double atomic per CTA ----
    float total = tot0 + tot1;
#pragma unroll
    for (int off = 16; off; off >>= 1)
        total += __shfl_xor_sync(0xffffffffu, total, off);
    if (lane == 0) red[wid] = total;
    __syncthreads();
    if (tid == 0) {
        double t = 0.0;
#pragma unroll
        for (int w = 0; w < 8; w++) t += (double)red[w];
        atomicAdd(&g_acc[accIdx], t);
    }
}

// ---------------------------------------------------------------------------
__global__ void finalize_kernel(float* out) {
    double a1 = g_acc[0] * (2.0 / ((double)NROWS * MROWS * DDIM));
    double b1 = g_acc[1] * (2.0 / ((double)NROWS * NROWS * DDIM));  // 2x: upper only
    double c1 = g_acc[2] * (2.0 / ((double)MROWS * MROWS * DDIM));
    out[0] = (float)(a1 - b1 - c1);
}

// ---------------------------------------------------------------------------
extern "C" void kernel_launch(void* const* d_in, const int* in_sizes, int n_in,
                              void* d_out, int out_size) {
    const float* lat = (const float*)d_in[0];
    const float* z   = (const float*)d_in[1];
    if (n_in >= 2 && in_sizes[0] == MROWS * DDIM && in_sizes[1] == NROWS * DDIM) {
        const float* t = lat; lat = z; z = t;
    }
    float* out = (float*)d_out;

    cudaFuncSetAttribute(pair_kernel,
                         cudaFuncAttributeMaxDynamicSharedMemorySize, SM_BYTES);

    prep_kernel<<<(32 * (NROWS + MROWS)) / 256, 256>>>(lat, z);
    pair_kernel<<<G_ALL, 256, SM_BYTES>>>();
    finalize_kernel<<<1, 1>>>(out);
}